// round 12
// baseline (speedup 1.0000x reference)
#include <cuda_runtime.h>
#include <cuda_fp16.h>
#include <math.h>

// ---------------------------------------------------------------------------
// DTree forward. Round 12: R9 (best, 811.8us) + work-stealing k6.
// 512 units (64 m-tiles x 4 n-quarters x 2 leaf-halves) dynamically grabbed
// by 296 persistent CTAs (2/SM uniform) -> kills the 86.5% fill curse.
// Units write disjoint g_part regions (deterministic); k7 = 2-way sum * scale.
// Per-warp GEMM code identical to R9 (64m x 32n warps, fp16 m16n8k16).
// ---------------------------------------------------------------------------

#define BATCH   8192
#define DIN     512
#define D1      513
#define HP      272      // g_hh row stride in u32 (half2 pairs): 544 halves
#define NKT     17
#define NODES   127
#define LEAVES  128
#define DOUT    256
#define UNITS   512
#define UITERS  (NKT * 64)   // 1088 iters per unit (64 leaves)

// prep_all block ranges
#define PB_LEAF 34816
#define PB_PRE  512
#define PB_RW   136
#define PB_NORM NODES

typedef unsigned long long u64;
typedef unsigned int u32;

// -------------------- scratch (device globals; no allocation) --------------
__device__ __align__(16) u32 g_hh[BATCH * HP];          // 8.9 MB packed half2 h
__device__ __align__(16) u32 g_Bp[LEAVES * NKT * 4096]; // 35.7 MB leaf B fragments
__device__ __align__(16) u32 g_Bpre[16 * 8192];         // 0.52 MB W_pre fragments
__device__ __align__(16) u32 g_Brw[NKT * 2048];         // 0.14 MB right_w fragments
__device__ __align__(16) float g_part[2 * BATCH * DOUT]; // 16.8 MB leaf-half partials
__device__ u32 g_swh2[LEAVES * BATCH];                  // 4.2 MB (s,s) half2
__device__ float g_right[BATCH * 128];
__device__ float g_invh[BATCH];
__device__ float g_invw[NODES];
__device__ float g_entpart[1024];
__device__ int   g_ctr;

// -------------------- helpers ----------------------------------------------
__device__ __forceinline__ u32 h2(float lo, float hi) {
    u32 r; asm("cvt.rn.f16x2.f32 %0, %1, %2;" : "=r"(r) : "f"(hi), "f"(lo)); return r;
}
__device__ __forceinline__ u32 hmul2(u32 a, u32 b) {
    u32 r; asm("mul.f16x2 %0, %1, %2;" : "=r"(r) : "r"(a), "r"(b)); return r;
}
__device__ __forceinline__ float2 h2f(u32 v) {
    __half2 h = *reinterpret_cast<__half2*>(&v);
    return __half22float2(h);
}
__device__ __forceinline__ void mma_f16(float* c, u32 a0, u32 a1, u32 a2, u32 a3,
                                        u32 b0, u32 b1) {
    asm volatile("mma.sync.aligned.m16n8k16.row.col.f32.f16.f16.f32 "
                 "{%0,%1,%2,%3}, {%4,%5,%6,%7}, {%8,%9}, {%0,%1,%2,%3};"
                 : "+f"(c[0]), "+f"(c[1]), "+f"(c[2]), "+f"(c[3])
                 : "r"(a0), "r"(a1), "r"(a2), "r"(a3), "r"(b0), "r"(b1));
}

// Fragment addressing convention (m16n8k16):
//   B frag u32 index = (((tile*NW + nw)*2 + ks)*2 + h)*128 + lane*4 + r
//   nt = h*2 + (r>>1); reg = r&1
//   n  = nw*32 + nt*8 + (lane>>2)
//   d  = kt*32 + ks*16 + (lane&3)*2 + reg*8   (value = half2(W[n][d], W[n][d+1]))

// ============================================================================
// k_prep_all: all weight preprocessing in one launch (R9 version).
// ============================================================================
__global__ void k_prep_all(const float* __restrict__ Wl, const float* __restrict__ bl,
                           const float* __restrict__ Wp, const float* __restrict__ rw) {
    int blk = blockIdx.x;
    if (blk < PB_LEAF) {
        u32 o = (u32)blk * 256 + threadIdx.x;
        u32 r = o & 3, lane = (o >> 2) & 31;
        u32 h = (o >> 7) & 1, ks = (o >> 8) & 1, nw = (o >> 9) & 7;
        u32 t = o >> 12;
        u32 kt = t % 17, l = t / 17;
        u32 nt = h * 2 + (r >> 1), reg = r & 1;
        int n = (int)(nw * 32 + nt * 8 + (lane >> 2));
        int row = (int)(l * 256 + n);
        int d = (int)(kt * 32 + ks * 16 + (lane & 3) * 2 + reg * 8);
        float v0 = 0.0f, v1 = 0.0f;
        if (d < D1)           v0 = Wl[(size_t)row * D1 + d];
        else if (d == D1)     v0 = bl[row];
        if (d + 1 < D1)       v1 = Wl[(size_t)row * D1 + d + 1];
        else if (d + 1 == D1) v1 = bl[row];
        g_Bp[o] = h2(v0, v1);
        return;
    }
    blk -= PB_LEAF;
    if (blk < PB_PRE) {
        u32 o = (u32)blk * 256 + threadIdx.x;   // < 131072
        u32 r = o & 3, lane = (o >> 2) & 31;
        u32 h = (o >> 7) & 1, ks = (o >> 8) & 1, nw = (o >> 9) & 15;
        u32 kt = o >> 13;
        u32 nt = h * 2 + (r >> 1), reg = r & 1;
        int n = (int)(nw * 32 + nt * 8 + (lane >> 2));
        int d = (int)(kt * 32 + ks * 16 + (lane & 3) * 2 + reg * 8);
        g_Bpre[o] = h2(Wp[(size_t)n * DIN + d], Wp[(size_t)n * DIN + d + 1]);
        return;
    }
    blk -= PB_PRE;
    if (blk < PB_RW) {
        u32 o = (u32)blk * 256 + threadIdx.x;   // < 34816
        u32 r = o & 3, lane = (o >> 2) & 31;
        u32 h = (o >> 7) & 1, ks = (o >> 8) & 1, nw = (o >> 9) & 3;
        u32 kt = o >> 11;
        u32 nt = h * 2 + (r >> 1), reg = r & 1;
        int n = (int)(nw * 32 + nt * 8 + (lane >> 2));
        int d = (int)(kt * 32 + ks * 16 + (lane & 3) * 2 + reg * 8);
        float v0 = (n < NODES && d < D1)     ? rw[(size_t)n * D1 + d]     : 0.0f;
        float v1 = (n < NODES && d + 1 < D1) ? rw[(size_t)n * D1 + d + 1] : 0.0f;
        g_Brw[o] = h2(v0, v1);
        return;
    }
    blk -= PB_RW;
    {   // inverse row norm for node blk
        __shared__ float sm[8];
        int n = blk, tid = threadIdx.x;
        const float* wr = rw + (size_t)n * D1;
        float s = 0.0f;
        for (int d = tid; d < D1; d += 256) { float v = wr[d]; s += v * v; }
        #pragma unroll
        for (int o = 16; o > 0; o >>= 1) s += __shfl_xor_sync(0xffffffffu, s, o);
        if ((tid & 31) == 0) sm[tid >> 5] = s;
        __syncthreads();
        if (tid == 0) {
            float t = 0.0f;
            #pragma unroll
            for (int i = 0; i < 8; i++) t += sm[i];
            g_invw[n] = 1.0f / fmaxf(sqrtf(t), 1e-12f);
        }
    }
}

// ============================================================================
// k1: h[:,0:512] = relu(x @ W_pre[0:512]^T + b_pre) -> g_hh pairs 0..255
// ============================================================================
__global__ __launch_bounds__(256, 1) void k1_pre(const float* __restrict__ x,
                                                 const float* __restrict__ bp) {
    int tid = threadIdx.x, wid = tid >> 5, lane = tid & 31;
    int mw = wid >> 2, nwl = wid & 3;
    int m0 = blockIdx.y * 128;
    int nw = blockIdx.x * 4 + nwl;
    int rbase = m0 + mw * 64 + (lane >> 2);

    const u32* Bb = g_Bpre + (size_t)nw * 512 + lane * 4;
    const float* Xb = x + (size_t)rbase * DIN + (lane & 3) * 2;

    float acc[4][4][4];
    #pragma unroll
    for (int a = 0; a < 4; a++)
        #pragma unroll
        for (int b = 0; b < 4; b++)
            #pragma unroll
            for (int c = 0; c < 4; c++) acc[a][b][c] = 0.0f;

    uint4 bb[2][2][2];
    #pragma unroll
    for (int ks = 0; ks < 2; ks++)
        #pragma unroll
        for (int h = 0; h < 2; h++)
            bb[0][ks][h] = __ldg((const uint4*)(Bb + ks * 256 + h * 128));

    #pragma unroll 2
    for (int kt = 0; kt < 16; kt++) {
        int pb = kt & 1, nb = pb ^ 1;
        if (kt + 1 < 16) {
            const u32* t = Bb + (size_t)(kt + 1) * 8192;
            #pragma unroll
            for (int ks = 0; ks < 2; ks++)
                #pragma unroll
                for (int h = 0; h < 2; h++)
                    bb[nb][ks][h] = __ldg((const uint4*)(t + ks * 256 + h * 128));
        }
        u32 av[4][2][2][2];
        #pragma unroll
        for (int mt = 0; mt < 4; mt++)
            #pragma unroll
            for (int rhl = 0; rhl < 2; rhl++)
                #pragma unroll
                for (int ks = 0; ks < 2; ks++)
                    #pragma unroll
                    for (int reg = 0; reg < 2; reg++) {
                        float2 f = *(const float2*)(Xb + (size_t)(mt * 16 + rhl * 8) * DIN
                                                    + kt * 32 + ks * 16 + reg * 8);
                        av[mt][rhl][ks][reg] = h2(f.x, f.y);
                    }
        #pragma unroll
        for (int ks = 0; ks < 2; ks++)
            #pragma unroll
            for (int h = 0; h < 2; h++) {
                uint4 B = bb[pb][ks][h];
                #pragma unroll
                for (int mt = 0; mt < 4; mt++) {
                    mma_f16(acc[mt][h * 2],     av[mt][0][ks][0], av[mt][1][ks][0],
                            av[mt][0][ks][1], av[mt][1][ks][1], B.x, B.y);
                    mma_f16(acc[mt][h * 2 + 1], av[mt][0][ks][0], av[mt][1][ks][0],
                            av[mt][0][ks][1], av[mt][1][ks][1], B.z, B.w);
                }
            }
    }

    int ncol = blockIdx.x * 128 + nwl * 32 + (lane & 3) * 2;
    #pragma unroll
    for (int mt = 0; mt < 4; mt++)
        #pragma unroll
        for (int half = 0; half < 2; half++) {
            int row = rbase + mt * 16 + half * 8;
            #pragma unroll
            for (int nt = 0; nt < 4; nt++) {
                int n = ncol + nt * 8;
                float v0 = fmaxf(acc[mt][nt][half * 2]     + __ldg(bp + n),     0.0f);
                float v1 = fmaxf(acc[mt][nt][half * 2 + 1] + __ldg(bp + n + 1), 0.0f);
                g_hh[(size_t)row * HP + (n >> 1)] = h2(v0, v1);
            }
        }
}

// ============================================================================
// k1b2: h[:,512] dot + pad writes + row inverse-norm. One warp per row.
// ============================================================================
__global__ void k1b2(const float* __restrict__ x, const float* __restrict__ Wp,
                     const float* __restrict__ bp) {
    int w = threadIdx.x >> 5, lane = threadIdx.x & 31;
    int b = blockIdx.x * 8 + w;
    const float* xr = x + (size_t)b * DIN;
    const float* wr = Wp + (size_t)512 * DIN;
    float s = 0.0f;
    #pragma unroll 4
    for (int d = lane; d < DIN; d += 32) s += xr[d] * wr[d];
    #pragma unroll
    for (int o = 16; o > 0; o >>= 1) s += __shfl_xor_sync(0xffffffffu, s, o);
    float h512 = fmaxf(s + __ldg(bp + 512), 0.0f);   // uniform across warp

    u32* row = g_hh + (size_t)b * HP;
    if (lane == 0) row[256] = h2(h512, 1.0f);
    else if (lane < 16) row[256 + lane] = 0u;

    float t = 0.0f;
    for (int i = lane; i < 256; i += 32) {
        float2 f = h2f(row[i]);
        t += f.x * f.x + f.y * f.y;
    }
    #pragma unroll
    for (int o = 16; o > 0; o >>= 1) t += __shfl_xor_sync(0xffffffffu, t, o);
    if (lane == 0) g_invh[b] = 1.0f / fmaxf(sqrtf(t + h512 * h512), 1e-12f);
}

// ============================================================================
// k3: right[b,n] = invh[b]*invw[n]*(h . right_w[n])  -- fp16 mma
// 128 CTAs x 128 thr: CTA tile 64m x 128n, one warp per 32-col n-slice.
// ============================================================================
__global__ __launch_bounds__(128, 2) void k3_right() {
    int tid = threadIdx.x, nwl = tid >> 5, lane = tid & 31;
    int m0 = blockIdx.x * 64;
    int rbase = m0 + (lane >> 2);

    const u32* Bb = g_Brw + (size_t)nwl * 512 + lane * 4;
    const u32* Hb = g_hh + (size_t)rbase * HP + (lane & 3);

    float acc[4][4][4];
    #pragma unroll
    for (int a = 0; a < 4; a++)
        #pragma unroll
        for (int b = 0; b < 4; b++)
            #pragma unroll
            for (int c = 0; c < 4; c++) acc[a][b][c] = 0.0f;

    #pragma unroll 1
    for (int kt = 0; kt < 17; kt++) {
        uint4 bb[2][2];
        #pragma unroll
        for (int ks = 0; ks < 2; ks++)
            #pragma unroll
            for (int h = 0; h < 2; h++)
                bb[ks][h] = __ldg((const uint4*)(Bb + (size_t)kt * 2048 + ks * 256 + h * 128));
        u32 hv[4][2][2][2];
        #pragma unroll
        for (int mt = 0; mt < 4; mt++)
            #pragma unroll
            for (int rhl = 0; rhl < 2; rhl++)
                #pragma unroll
                for (int ks = 0; ks < 2; ks++)
                    #pragma unroll
                    for (int reg = 0; reg < 2; reg++)
                        hv[mt][rhl][ks][reg] = __ldg(Hb + (size_t)(mt * 16 + rhl * 8) * HP
                                                     + kt * 16 + ks * 8 + reg * 4);
        #pragma unroll
        for (int ks = 0; ks < 2; ks++)
            #pragma unroll
            for (int h = 0; h < 2; h++) {
                uint4 B = bb[ks][h];
                #pragma unroll
                for (int mt = 0; mt < 4; mt++) {
                    mma_f16(acc[mt][h * 2],     hv[mt][0][ks][0], hv[mt][1][ks][0],
                            hv[mt][0][ks][1], hv[mt][1][ks][1], B.x, B.y);
                    mma_f16(acc[mt][h * 2 + 1], hv[mt][0][ks][0], hv[mt][1][ks][0],
                            hv[mt][0][ks][1], hv[mt][1][ks][1], B.z, B.w);
                }
            }
    }

    #pragma unroll
    for (int mt = 0; mt < 4; mt++)
        #pragma unroll
        for (int half = 0; half < 2; half++) {
            int row = rbase + mt * 16 + half * 8;
            float ih = g_invh[row];
            #pragma unroll
            for (int nt = 0; nt < 4; nt++) {
                int n = nwl * 32 + nt * 8 + (lane & 3) * 2;
                if (n < NODES)
                    g_right[(size_t)row * 128 + n] = acc[mt][nt][half * 2] * ih * g_invw[n];
                if (n + 1 < NODES)
                    g_right[(size_t)row * 128 + n + 1] = acc[mt][nt][half * 2 + 1] * ih * g_invw[n + 1];
            }
        }
}

// ============================================================================
// k4: routing -> g_swh2 (packed (s,s) half2, [l][b]), entropy partials.
// Also resets the k6 work-stealing counter (runs before k6 every replay).
// ============================================================================
__global__ __launch_bounds__(256) void k4_route(const int* __restrict__ ridx,
                                                const int* __restrict__ rside) {
    __shared__ int s_idx[LEAVES * 7];
    __shared__ int s_side[LEAVES * 7];
    __shared__ float s_lr[8][128];
    __shared__ float s_ll[8][128];
    __shared__ float s_ent[8];

    int tid = threadIdx.x;
    if (tid == 0 && blockIdx.x == 0) g_ctr = 0;
    for (int t = tid; t < LEAVES * 7; t += 256) { s_idx[t] = ridx[t]; s_side[t] = rside[t]; }
    __syncthreads();

    int w = tid / 32, lane = tid % 32;
    int b = blockIdx.x * 8 + w;

    for (int n = lane; n < NODES; n += 32) {
        float r = g_right[b * 128 + n];
        float rd = 0.5f * (1.0f - r);
        float ld = 0.5f * (1.0f + r);
        s_lr[w][n] = logf(fminf(fmaxf(rd, 0.01f), 0.99f));
        s_ll[w][n] = logf(fminf(fmaxf(ld, 0.01f), 0.99f));
    }
    __syncwarp();

    float ent = 0.0f;
    for (int li = lane; li < LEAVES; li += 32) {
        float lp = 0.0f;
        #pragma unroll
        for (int j = 0; j < 7; j++) {
            int node = s_idx[li * 7 + j];
            int side = s_side[li * 7 + j];
            lp += side ? s_ll[w][node] : s_lr[w][node];
        }
        float s = expf(lp);
        g_swh2[li * BATCH + b] = h2(s, s);
        ent -= s * lp;
    }
    #pragma unroll
    for (int o = 16; o > 0; o >>= 1) ent += __shfl_xor_sync(0xffffffffu, ent, o);
    if (lane == 0) s_ent[w] = ent;
    __syncthreads();
    if (tid == 0) {
        float t = 0.0f;
        #pragma unroll
        for (int i = 0; i < 8; i++) t += s_ent[i];
        g_entpart[blockIdx.x] = t;
    }
}

// ============================================================================
// k6: fp16 mma leaf contraction, work-stealing persistent CTAs.
// 296 CTAs x 128 thr (2/SM uniform), R9 warp geometry (2 n-slices x 2
// m-halves, warp tile 64m x 32n). Units: u = (half<<8)|(tn<<6)|tm ->
// tile (tm*128 m, tn*64 n), leaves [half*64, half*64+64). Consecutive units
// share B (same half, tn). Each unit writes its disjoint g_part[half] slice.
// ============================================================================
__global__ __launch_bounds__(128, 2) void k6_mma() {
    __shared__ int s_u;
    int tid = threadIdx.x, wid = tid >> 5, lane = tid & 31;
    int mw = wid >> 1, nwl = wid & 1;

    for (;;) {
        if (tid == 0) s_u = atomicAdd(&g_ctr, 1);
        __syncthreads();
        int u = s_u;
        __syncthreads();
        if (u >= UNITS) break;

        int half = u >> 8;
        int tn = (u >> 6) & 3;
        int tm = u & 63;
        int l0 = half * 64;
        int m0 = tm * 128;
        int nw = tn * 2 + nwl;
        int rbase = m0 + mw * 64 + (lane >> 2);

        const u32* Bb = g_Bp + (size_t)nw * 512 + lane * 4;   // + (l*17+kt)*4096
        const u32* SWb = g_swh2 + (size_t)l0 * BATCH + rbase;
        const u32* Hb = g_hh + (size_t)rbase * HP + (lane & 3);

        float acc[4][4][4];
        #pragma unroll
        for (int a = 0; a < 4; a++)
            #pragma unroll
            for (int b = 0; b < 4; b++)
                #pragma unroll
                for (int c = 0; c < 4; c++) acc[a][b][c] = 0.0f;

        uint4 bb[2][2][2];       // [buf][ks][h]
        u32 sw[2][8];            // [buf][mt*2 + rhl]
        u32 hv[4][2][2][2];      // [mt][rhl][ks][reg]

        // preload it=0 (kt=0, l=l0)
        {
            const u32* t = Bb + (size_t)(l0 * 17) * 4096;
            #pragma unroll
            for (int ks = 0; ks < 2; ks++)
                #pragma unroll
                for (int h = 0; h < 2; h++)
                    bb[0][ks][h] = __ldg((const uint4*)(t + ks * 256 + h * 128));
            #pragma unroll
            for (int j = 0; j < 8; j++)
                sw[0][j] = __ldg(SWb + (j >> 1) * 16 + (j & 1) * 8);
        }

        int it = 0;
        #pragma unroll 1
        for (int kt = 0; kt < NKT; kt++) {
            #pragma unroll
            for (int mt = 0; mt < 4; mt++)
                #pragma unroll
                for (int rhl = 0; rhl < 2; rhl++)
                    #pragma unroll
                    for (int ks = 0; ks < 2; ks++)
                        #pragma unroll
                        for (int reg = 0; reg < 2; reg++)
                            hv[mt][rhl][ks][reg] = __ldg(Hb + (size_t)(mt * 16 + rhl * 8) * HP
                                                         + kt * 16 + ks * 8 + reg * 4);
            #pragma unroll 2
            for (int li = 0; li < 64; li++) {
                int pb = it & 1, nb = pb ^ 1;
                int nit = it + 1;
                if (nit < UITERS) {
                    int nl = nit & 63, nkt = nit >> 6;
                    const u32* t = Bb + (size_t)((l0 + nl) * 17 + nkt) * 4096;
                    #pragma unroll
                    for (int ks = 0; ks < 2; ks++)
                        #pragma unroll
                        for (int h = 0; h < 2; h++)
                            bb[nb][ks][h] = __ldg((const uint4*)(t + ks * 256 + h * 128));
                    const u32* sp = SWb + (size_t)nl * BATCH;
                    #pragma unroll
                    for (int j = 0; j < 8; j++)
                        sw[nb][j] = __ldg(sp + (j >> 1) * 16 + (j & 1) * 8);
                }
                #pragma unroll
                for (int ks = 0; ks < 2; ks++) {
                    u32 A0[4], A1[4], A2[4], A3[4];
                    #pragma unroll
                    for (int mt = 0; mt < 4; mt++) {
                        A0[mt] = hmul2(hv[mt][0][ks][0], sw[pb][mt * 2]);
                        A1[mt] = hmul2(hv[mt][1][ks][0], sw[pb][mt * 2 + 1]);
                        A2[mt] = hmul2(hv[mt][0][ks][1], sw[pb][mt * 2]);
                        A3[mt] = hmul2(hv[mt][1][ks][1], sw[pb][mt * 2 + 1]);
                    }
                    #pragma unroll
                    for (int h = 0; h < 2; h++) {
                        uint4 B = bb[pb][ks][h];
                        #pragma unroll
                        for (int mt = 0; mt < 4; mt++) {
                            mma_f16(acc[mt][h * 2],     A0[mt], A1[mt], A2[mt], A3[mt], B.x, B.y);
                            mma_f16(acc[mt][h * 2 + 1], A0[mt], A1[mt], A2[mt], A3[mt], B.z, B.w);
                        }
                    }
                }
                it++;
            }
        }

        // write this unit's partial (disjoint region; no scale here)
        float* part = g_part + (size_t)half * BATCH * DOUT;
        int ncol = tn * 64 + nwl * 32 + (lane & 3) * 2;
        #pragma unroll
        for (int mt = 0; mt < 4; mt++)
            #pragma unroll
            for (int hf = 0; hf < 2; hf++) {
                int row = rbase + mt * 16 + hf * 8;
                float* op = part + (size_t)row * DOUT + ncol;
                #pragma unroll
                for (int nt = 0; nt < 4; nt++) {
                    float2 v;
                    v.x = acc[mt][nt][hf * 2];
                    v.y = acc[mt][nt][hf * 2 + 1];
                    *(float2*)(op + nt * 8) = v;
                }
            }
    }
}

// ============================================================================
// k7: out = scale * (part0 + part1). Deterministic fixed-order sum.
// ============================================================================
__global__ __launch_bounds__(256) void k7_out(float* __restrict__ out) {
    __shared__ float sm[256];
    int tid = threadIdx.x;
    {
        float s = 0.0f;
        #pragma unroll
        for (int i = 0; i < 4; i++) s += g_entpart[tid + i * 256];
        sm[tid] = s;
    }
    __syncthreads();
    #pragma unroll
    for (int st = 128; st > 0; st >>= 1) {
        if (tid < st) sm[tid] += sm[tid + st];
        __syncthreads();
    }
    float max_ent = (128.0f / 6.0f) * logf(6.0f);
    float sc = 1.0f + (sm[0] / (float)BATCH) / max_ent;

    size_t i = ((size_t)blockIdx.x * 256 + tid) * 4;
    float4 a = *(const float4*)(g_part + i);
    float4 b = *(const float4*)(g_part + (size_t)BATCH * DOUT + i);
    float4 v;
    v.x = (a.x + b.x) * sc;
    v.y = (a.y + b.y) * sc;
    v.z = (a.z + b.z) * sc;
    v.w = (a.w + b.w) * sc;
    *(float4*)(out + i) = v;
}

// ============================================================================
extern "C" void kernel_launch(void* const* d_in, const int* in_sizes, int n_in,
                              void* d_out, int out_size) {
    const float* x      = (const float*)d_in[0];
    const float* W_pre  = (const float*)d_in[1];
    const float* b_pre  = (const float*)d_in[2];
    const float* rw     = (const float*)d_in[3];
    const float* W_leaf = (const float*)d_in[4];
    const float* b_leaf = (const float*)d_in[5];
    const int*   ridx   = (const int*)d_in[6];
    const int*   rside  = (const int*)d_in[7];
    float* out = (float*)d_out;

    k_prep_all<<<PB_LEAF + PB_PRE + PB_RW + PB_NORM, 256>>>(W_leaf, b_leaf, W_pre, rw);
    k1_pre<<<dim3(4, 64), 256>>>(x, b_pre);
    k1b2<<<1024, 256>>>(x, W_pre, b_pre);
    k3_right<<<128, 128>>>();
    k4_route<<<1024, 256>>>(ridx, rside);
    k6_mma<<<296, 128>>>();              // launch index 5 -> ncu capture slot
    k7_out<<<2048, 256>>>(out);
}

// round 13
// speedup vs baseline: 1.3360x; 1.3360x over previous
#include <cuda_runtime.h>
#include <cuda_fp16.h>
#include <math.h>

// ---------------------------------------------------------------------------
// DTree forward. Round 13: exact R9 structure (best measured, 811.8us;
// R6/R12 scheduling rewrites both regressed and are abandoned) + one
// bounded win: k4 routing transcendentals -> __logf/__expf (MUFU).
// All GEMMs on mma.sync.m16n8k16.f16 with pre-permuted B fragments, no smem.
// k6: 256 CTAs x 128 thr, CTA tile 128m x 64n (2 n-slices x 2 m-halves),
// block-uniform addressing (load-bearing for ptxas uniform registers).
// ---------------------------------------------------------------------------

#define BATCH   8192
#define DIN     512
#define D1      513
#define HP      272      // g_hh row stride in u32 (half2 pairs): 544 halves
#define NKT     17
#define NODES   127
#define LEAVES  128
#define DOUT    256
#define ITERS   (NKT * LEAVES)   // 2176

// prep_all block ranges
#define PB_LEAF 34816
#define PB_PRE  512
#define PB_RW   136
#define PB_NORM NODES

typedef unsigned long long u64;
typedef unsigned int u32;

// -------------------- scratch (device globals; no allocation) --------------
__device__ __align__(16) u32 g_hh[BATCH * HP];          // 8.9 MB packed half2 h
__device__ __align__(16) u32 g_Bp[LEAVES * NKT * 4096]; // 35.7 MB leaf B fragments
__device__ __align__(16) u32 g_Bpre[16 * 8192];         // 0.52 MB W_pre fragments
__device__ __align__(16) u32 g_Brw[NKT * 2048];         // 0.14 MB right_w fragments
__device__ u32 g_swh2[LEAVES * BATCH];                  // 4.2 MB (s,s) half2
__device__ float g_right[BATCH * 128];
__device__ float g_invh[BATCH];
__device__ float g_invw[NODES];
__device__ float g_entpart[1024];

// -------------------- helpers ----------------------------------------------
__device__ __forceinline__ u32 h2(float lo, float hi) {
    u32 r; asm("cvt.rn.f16x2.f32 %0, %1, %2;" : "=r"(r) : "f"(hi), "f"(lo)); return r;
}
__device__ __forceinline__ u32 hmul2(u32 a, u32 b) {
    u32 r; asm("mul.f16x2 %0, %1, %2;" : "=r"(r) : "r"(a), "r"(b)); return r;
}
__device__ __forceinline__ float2 h2f(u32 v) {
    __half2 h = *reinterpret_cast<__half2*>(&v);
    return __half22float2(h);
}
__device__ __forceinline__ void mma_f16(float* c, u32 a0, u32 a1, u32 a2, u32 a3,
                                        u32 b0, u32 b1) {
    asm volatile("mma.sync.aligned.m16n8k16.row.col.f32.f16.f16.f32 "
                 "{%0,%1,%2,%3}, {%4,%5,%6,%7}, {%8,%9}, {%0,%1,%2,%3};"
                 : "+f"(c[0]), "+f"(c[1]), "+f"(c[2]), "+f"(c[3])
                 : "r"(a0), "r"(a1), "r"(a2), "r"(a3), "r"(b0), "r"(b1));
}

// Fragment addressing convention (m16n8k16):
//   B frag u32 index = (((tile*NW + nw)*2 + ks)*2 + h)*128 + lane*4 + r
//   nt = h*2 + (r>>1); reg = r&1
//   n  = nw*32 + nt*8 + (lane>>2)
//   d  = kt*32 + ks*16 + (lane&3)*2 + reg*8   (value = half2(W[n][d], W[n][d+1]))

// ============================================================================
// k_prep_all: all weight preprocessing in one launch.
// ============================================================================
__global__ void k_prep_all(const float* __restrict__ Wl, const float* __restrict__ bl,
                           const float* __restrict__ Wp, const float* __restrict__ rw) {
    int blk = blockIdx.x;
    if (blk < PB_LEAF) {
        u32 o = (u32)blk * 256 + threadIdx.x;
        u32 r = o & 3, lane = (o >> 2) & 31;
        u32 h = (o >> 7) & 1, ks = (o >> 8) & 1, nw = (o >> 9) & 7;
        u32 t = o >> 12;
        u32 kt = t % 17, l = t / 17;
        u32 nt = h * 2 + (r >> 1), reg = r & 1;
        int n = (int)(nw * 32 + nt * 8 + (lane >> 2));
        int row = (int)(l * 256 + n);
        int d = (int)(kt * 32 + ks * 16 + (lane & 3) * 2 + reg * 8);
        float v0 = 0.0f, v1 = 0.0f;
        if (d < D1)           v0 = Wl[(size_t)row * D1 + d];
        else if (d == D1)     v0 = bl[row];
        if (d + 1 < D1)       v1 = Wl[(size_t)row * D1 + d + 1];
        else if (d + 1 == D1) v1 = bl[row];
        g_Bp[o] = h2(v0, v1);
        return;
    }
    blk -= PB_LEAF;
    if (blk < PB_PRE) {
        u32 o = (u32)blk * 256 + threadIdx.x;   // < 131072
        u32 r = o & 3, lane = (o >> 2) & 31;
        u32 h = (o >> 7) & 1, ks = (o >> 8) & 1, nw = (o >> 9) & 15;
        u32 kt = o >> 13;
        u32 nt = h * 2 + (r >> 1), reg = r & 1;
        int n = (int)(nw * 32 + nt * 8 + (lane >> 2));
        int d = (int)(kt * 32 + ks * 16 + (lane & 3) * 2 + reg * 8);
        g_Bpre[o] = h2(Wp[(size_t)n * DIN + d], Wp[(size_t)n * DIN + d + 1]);
        return;
    }
    blk -= PB_PRE;
    if (blk < PB_RW) {
        u32 o = (u32)blk * 256 + threadIdx.x;   // < 34816
        u32 r = o & 3, lane = (o >> 2) & 31;
        u32 h = (o >> 7) & 1, ks = (o >> 8) & 1, nw = (o >> 9) & 3;
        u32 kt = o >> 11;
        u32 nt = h * 2 + (r >> 1), reg = r & 1;
        int n = (int)(nw * 32 + nt * 8 + (lane >> 2));
        int d = (int)(kt * 32 + ks * 16 + (lane & 3) * 2 + reg * 8);
        float v0 = (n < NODES && d < D1)     ? rw[(size_t)n * D1 + d]     : 0.0f;
        float v1 = (n < NODES && d + 1 < D1) ? rw[(size_t)n * D1 + d + 1] : 0.0f;
        g_Brw[o] = h2(v0, v1);
        return;
    }
    blk -= PB_RW;
    {   // inverse row norm for node blk
        __shared__ float sm[8];
        int n = blk, tid = threadIdx.x;
        const float* wr = rw + (size_t)n * D1;
        float s = 0.0f;
        for (int d = tid; d < D1; d += 256) { float v = wr[d]; s += v * v; }
        #pragma unroll
        for (int o = 16; o > 0; o >>= 1) s += __shfl_xor_sync(0xffffffffu, s, o);
        if ((tid & 31) == 0) sm[tid >> 5] = s;
        __syncthreads();
        if (tid == 0) {
            float t = 0.0f;
            #pragma unroll
            for (int i = 0; i < 8; i++) t += sm[i];
            g_invw[n] = 1.0f / fmaxf(sqrtf(t), 1e-12f);
        }
    }
}

// ============================================================================
// k1: h[:,0:512] = relu(x @ W_pre[0:512]^T + b_pre) -> g_hh pairs 0..255
// ============================================================================
__global__ __launch_bounds__(256, 1) void k1_pre(const float* __restrict__ x,
                                                 const float* __restrict__ bp) {
    int tid = threadIdx.x, wid = tid >> 5, lane = tid & 31;
    int mw = wid >> 2, nwl = wid & 3;
    int m0 = blockIdx.y * 128;
    int nw = blockIdx.x * 4 + nwl;
    int rbase = m0 + mw * 64 + (lane >> 2);

    const u32* Bb = g_Bpre + (size_t)nw * 512 + lane * 4;
    const float* Xb = x + (size_t)rbase * DIN + (lane & 3) * 2;

    float acc[4][4][4];
    #pragma unroll
    for (int a = 0; a < 4; a++)
        #pragma unroll
        for (int b = 0; b < 4; b++)
            #pragma unroll
            for (int c = 0; c < 4; c++) acc[a][b][c] = 0.0f;

    uint4 bb[2][2][2];
    #pragma unroll
    for (int ks = 0; ks < 2; ks++)
        #pragma unroll
        for (int h = 0; h < 2; h++)
            bb[0][ks][h] = __ldg((const uint4*)(Bb + ks * 256 + h * 128));

    #pragma unroll 2
    for (int kt = 0; kt < 16; kt++) {
        int pb = kt & 1, nb = pb ^ 1;
        if (kt + 1 < 16) {
            const u32* t = Bb + (size_t)(kt + 1) * 8192;
            #pragma unroll
            for (int ks = 0; ks < 2; ks++)
                #pragma unroll
                for (int h = 0; h < 2; h++)
                    bb[nb][ks][h] = __ldg((const uint4*)(t + ks * 256 + h * 128));
        }
        u32 av[4][2][2][2];
        #pragma unroll
        for (int mt = 0; mt < 4; mt++)
            #pragma unroll
            for (int rhl = 0; rhl < 2; rhl++)
                #pragma unroll
                for (int ks = 0; ks < 2; ks++)
                    #pragma unroll
                    for (int reg = 0; reg < 2; reg++) {
                        float2 f = *(const float2*)(Xb + (size_t)(mt * 16 + rhl * 8) * DIN
                                                    + kt * 32 + ks * 16 + reg * 8);
                        av[mt][rhl][ks][reg] = h2(f.x, f.y);
                    }
        #pragma unroll
        for (int ks = 0; ks < 2; ks++)
            #pragma unroll
            for (int h = 0; h < 2; h++) {
                uint4 B = bb[pb][ks][h];
                #pragma unroll
                for (int mt = 0; mt < 4; mt++) {
                    mma_f16(acc[mt][h * 2],     av[mt][0][ks][0], av[mt][1][ks][0],
                            av[mt][0][ks][1], av[mt][1][ks][1], B.x, B.y);
                    mma_f16(acc[mt][h * 2 + 1], av[mt][0][ks][0], av[mt][1][ks][0],
                            av[mt][0][ks][1], av[mt][1][ks][1], B.z, B.w);
                }
            }
    }

    int ncol = blockIdx.x * 128 + nwl * 32 + (lane & 3) * 2;
    #pragma unroll
    for (int mt = 0; mt < 4; mt++)
        #pragma unroll
        for (int half = 0; half < 2; half++) {
            int row = rbase + mt * 16 + half * 8;
            #pragma unroll
            for (int nt = 0; nt < 4; nt++) {
                int n = ncol + nt * 8;
                float v0 = fmaxf(acc[mt][nt][half * 2]     + __ldg(bp + n),     0.0f);
                float v1 = fmaxf(acc[mt][nt][half * 2 + 1] + __ldg(bp + n + 1), 0.0f);
                g_hh[(size_t)row * HP + (n >> 1)] = h2(v0, v1);
            }
        }
}

// ============================================================================
// k1b2: h[:,512] dot + pad writes + row inverse-norm. One warp per row.
// ============================================================================
__global__ void k1b2(const float* __restrict__ x, const float* __restrict__ Wp,
                     const float* __restrict__ bp) {
    int w = threadIdx.x >> 5, lane = threadIdx.x & 31;
    int b = blockIdx.x * 8 + w;
    const float* xr = x + (size_t)b * DIN;
    const float* wr = Wp + (size_t)512 * DIN;
    float s = 0.0f;
    #pragma unroll 4
    for (int d = lane; d < DIN; d += 32) s += xr[d] * wr[d];
    #pragma unroll
    for (int o = 16; o > 0; o >>= 1) s += __shfl_xor_sync(0xffffffffu, s, o);
    float h512 = fmaxf(s + __ldg(bp + 512), 0.0f);   // uniform across warp

    u32* row = g_hh + (size_t)b * HP;
    if (lane == 0) row[256] = h2(h512, 1.0f);
    else if (lane < 16) row[256 + lane] = 0u;

    float t = 0.0f;
    for (int i = lane; i < 256; i += 32) {
        float2 f = h2f(row[i]);
        t += f.x * f.x + f.y * f.y;
    }
    #pragma unroll
    for (int o = 16; o > 0; o >>= 1) t += __shfl_xor_sync(0xffffffffu, t, o);
    if (lane == 0) g_invh[b] = 1.0f / fmaxf(sqrtf(t + h512 * h512), 1e-12f);
}

// ============================================================================
// k3: right[b,n] = invh[b]*invw[n]*(h . right_w[n])  -- fp16 mma
// 128 CTAs x 128 thr: CTA tile 64m x 128n, one warp per 32-col n-slice.
// ============================================================================
__global__ __launch_bounds__(128, 2) void k3_right() {
    int tid = threadIdx.x, nwl = tid >> 5, lane = tid & 31;
    int m0 = blockIdx.x * 64;
    int rbase = m0 + (lane >> 2);

    const u32* Bb = g_Brw + (size_t)nwl * 512 + lane * 4;
    const u32* Hb = g_hh + (size_t)rbase * HP + (lane & 3);

    float acc[4][4][4];
    #pragma unroll
    for (int a = 0; a < 4; a++)
        #pragma unroll
        for (int b = 0; b < 4; b++)
            #pragma unroll
            for (int c = 0; c < 4; c++) acc[a][b][c] = 0.0f;

    #pragma unroll 1
    for (int kt = 0; kt < 17; kt++) {
        uint4 bb[2][2];
        #pragma unroll
        for (int ks = 0; ks < 2; ks++)
            #pragma unroll
            for (int h = 0; h < 2; h++)
                bb[ks][h] = __ldg((const uint4*)(Bb + (size_t)kt * 2048 + ks * 256 + h * 128));
        u32 hv[4][2][2][2];
        #pragma unroll
        for (int mt = 0; mt < 4; mt++)
            #pragma unroll
            for (int rhl = 0; rhl < 2; rhl++)
                #pragma unroll
                for (int ks = 0; ks < 2; ks++)
                    #pragma unroll
                    for (int reg = 0; reg < 2; reg++)
                        hv[mt][rhl][ks][reg] = __ldg(Hb + (size_t)(mt * 16 + rhl * 8) * HP
                                                     + kt * 16 + ks * 8 + reg * 4);
        #pragma unroll
        for (int ks = 0; ks < 2; ks++)
            #pragma unroll
            for (int h = 0; h < 2; h++) {
                uint4 B = bb[ks][h];
                #pragma unroll
                for (int mt = 0; mt < 4; mt++) {
                    mma_f16(acc[mt][h * 2],     hv[mt][0][ks][0], hv[mt][1][ks][0],
                            hv[mt][0][ks][1], hv[mt][1][ks][1], B.x, B.y);
                    mma_f16(acc[mt][h * 2 + 1], hv[mt][0][ks][0], hv[mt][1][ks][0],
                            hv[mt][0][ks][1], hv[mt][1][ks][1], B.z, B.w);
                }
            }
    }

    #pragma unroll
    for (int mt = 0; mt < 4; mt++)
        #pragma unroll
        for (int half = 0; half < 2; half++) {
            int row = rbase + mt * 16 + half * 8;
            float ih = g_invh[row];
            #pragma unroll
            for (int nt = 0; nt < 4; nt++) {
                int n = nwl * 32 + nt * 8 + (lane & 3) * 2;
                if (n < NODES)
                    g_right[(size_t)row * 128 + n] = acc[mt][nt][half * 2] * ih * g_invw[n];
                if (n + 1 < NODES)
                    g_right[(size_t)row * 128 + n + 1] = acc[mt][nt][half * 2 + 1] * ih * g_invw[n + 1];
            }
        }
}

// ============================================================================
// k4: routing -> g_swh2 (packed (s,s) half2, [l][b]), entropy partials.
// Transcendentals via MUFU intrinsics (__logf/__expf): inputs clipped to
// [0.01, 0.99], intrinsic error ~2^-21 -> s_w perturbation ~1e-6.
// ============================================================================
__global__ __launch_bounds__(256) void k4_route(const int* __restrict__ ridx,
                                                const int* __restrict__ rside) {
    __shared__ int s_idx[LEAVES * 7];
    __shared__ int s_side[LEAVES * 7];
    __shared__ float s_lr[8][128];
    __shared__ float s_ll[8][128];
    __shared__ float s_ent[8];

    int tid = threadIdx.x;
    for (int t = tid; t < LEAVES * 7; t += 256) { s_idx[t] = ridx[t]; s_side[t] = rside[t]; }
    __syncthreads();

    int w = tid / 32, lane = tid % 32;
    int b = blockIdx.x * 8 + w;

    for (int n = lane; n < NODES; n += 32) {
        float r = g_right[b * 128 + n];
        float rd = 0.5f * (1.0f - r);
        float ld = 0.5f * (1.0f + r);
        s_lr[w][n] = __logf(fminf(fmaxf(rd, 0.01f), 0.99f));
        s_ll[w][n] = __logf(fminf(fmaxf(ld, 0.01f), 0.99f));
    }
    __syncwarp();

    float ent = 0.0f;
    for (int li = lane; li < LEAVES; li += 32) {
        float lp = 0.0f;
        #pragma unroll
        for (int j = 0; j < 7; j++) {
            int node = s_idx[li * 7 + j];
            int side = s_side[li * 7 + j];
            lp += side ? s_ll[w][node] : s_lr[w][node];
        }
        float s = __expf(lp);
        g_swh2[li * BATCH + b] = h2(s, s);
        ent -= s * lp;
    }
    #pragma unroll
    for (int o = 16; o > 0; o >>= 1) ent += __shfl_xor_sync(0xffffffffu, ent, o);
    if (lane == 0) s_ent[w] = ent;
    __syncthreads();
    if (tid == 0) {
        float t = 0.0f;
        #pragma unroll
        for (int i = 0; i < 8; i++) t += s_ent[i];
        g_entpart[blockIdx.x] = t;
    }
}

// ============================================================================
// k6: fp16 mma leaf contraction. 256 CTAs x 128 thr, CTA tile 128m x 64n
// (2 n-slice warps x 2 m-half warps; m-pair B loads dedup in L1).
// Scale reduction from g_entpart inline in epilogue (deterministic).
// ============================================================================
__global__ __launch_bounds__(128, 2) void k6_mma(float* __restrict__ out) {
    int tid = threadIdx.x, wid = tid >> 5, lane = tid & 31;
    int mw = wid >> 1, nwl = wid & 1;
    int m0 = blockIdx.y * 128;
    int nw = blockIdx.x * 2 + nwl;
    int rbase = m0 + mw * 64 + (lane >> 2);

    const u32* Bb = g_Bp + (size_t)nw * 512 + lane * 4;     // + tile*4096 (+ks*256+h*128)
    const u32* SWb = g_swh2 + rbase;
    const u32* Hb = g_hh + (size_t)rbase * HP + (lane & 3);

    float acc[4][4][4];
    #pragma unroll
    for (int a = 0; a < 4; a++)
        #pragma unroll
        for (int b = 0; b < 4; b++)
            #pragma unroll
            for (int c = 0; c < 4; c++) acc[a][b][c] = 0.0f;

    uint4 bb[2][2][2];       // [buf][ks][h]
    u32 sw[2][8];            // [buf][mt*2 + rhl]
    u32 hv[4][2][2][2];      // [mt][rhl][ks][reg]

    // preload it=0 (kt=0, l=0)
    #pragma unroll
    for (int ks = 0; ks < 2; ks++)
        #pragma unroll
        for (int h = 0; h < 2; h++)
            bb[0][ks][h] = __ldg((const uint4*)(Bb + ks * 256 + h * 128));
    #pragma unroll
    for (int j = 0; j < 8; j++)
        sw[0][j] = __ldg(SWb + (j >> 1) * 16 + (j & 1) * 8);

    int it = 0;
    #pragma unroll 1
    for (int kt = 0; kt < NKT; kt++) {
        #pragma unroll
        for (int mt = 0; mt < 4; mt++)
            #pragma unroll
            for (int rhl = 0; rhl < 2; rhl++)
                #pragma unroll
                for (int ks = 0; ks < 2; ks++)
                    #pragma unroll
                    for (int reg = 0; reg < 2; reg++)
                        hv[mt][rhl][ks][reg] = __ldg(Hb + (size_t)(mt * 16 + rhl * 8) * HP
                                                     + kt * 16 + ks * 8 + reg * 4);
        #pragma unroll 2
        for (int l = 0; l < LEAVES; l++) {
            int pb = l & 1, nb = pb ^ 1;
            int nit = it + 1;
            if (nit < ITERS) {
                int nl = nit & 127, nkt = nit >> 7;
                const u32* t = Bb + (size_t)(nl * 17 + nkt) * 4096;
                #pragma unroll
                for (int ks = 0; ks < 2; ks++)
                    #pragma unroll
                    for (int h = 0; h < 2; h++)
                        bb[nb][ks][h] = __ldg((const uint4*)(t + ks * 256 + h * 128));
                const u32* sp = SWb + (size_t)nl * BATCH;
                #pragma unroll
                for (int j = 0; j < 8; j++)
                    sw[nb][j] = __ldg(sp + (j >> 1) * 16 + (j & 1) * 8);
            }
            #pragma unroll
            for (int ks = 0; ks < 2; ks++) {
                u32 A0[4], A1[4], A2[4], A3[4];
                #pragma unroll
                for (int mt = 0; mt < 4; mt++) {
                    A0[mt] = hmul2(hv[mt][0][ks][0], sw[pb][mt * 2]);
                    A1[mt] = hmul2(hv[mt][1][ks][0], sw[pb][mt * 2 + 1]);
                    A2[mt] = hmul2(hv[mt][0][ks][1], sw[pb][mt * 2]);
                    A3[mt] = hmul2(hv[mt][1][ks][1], sw[pb][mt * 2 + 1]);
                }
                #pragma unroll
                for (int h = 0; h < 2; h++) {
                    uint4 B = bb[pb][ks][h];
                    #pragma unroll
                    for (int mt = 0; mt < 4; mt++) {
                        mma_f16(acc[mt][h * 2],     A0[mt], A1[mt], A2[mt], A3[mt], B.x, B.y);
                        mma_f16(acc[mt][h * 2 + 1], A0[mt], A1[mt], A2[mt], A3[mt], B.z, B.w);
                    }
                }
            }
            it++;
        }
    }

    // inline deterministic scale = 1 + (sum(entpart)/BATCH)/max_ent
    __shared__ float sm[128];
    {
        float s = 0.0f;
        #pragma unroll
        for (int i = 0; i < 8; i++) s += g_entpart[tid + i * 128];
        sm[tid] = s;
    }
    __syncthreads();
    #pragma unroll
    for (int st = 64; st > 0; st >>= 1) {
        if (tid < st) sm[tid] += sm[tid + st];
        __syncthreads();
    }
    float max_ent = (128.0f / 6.0f) * logf(6.0f);
    float sc = 1.0f + (sm[0] / (float)BATCH) / max_ent;

    int ncol = blockIdx.x * 64 + nwl * 32 + (lane & 3) * 2;
    #pragma unroll
    for (int mt = 0; mt < 4; mt++)
        #pragma unroll
        for (int half = 0; half < 2; half++) {
            int row = rbase + mt * 16 + half * 8;
            float* op = out + (size_t)row * DOUT + ncol;
            #pragma unroll
            for (int nt = 0; nt < 4; nt++) {
                float2 v;
                v.x = acc[mt][nt][half * 2] * sc;
                v.y = acc[mt][nt][half * 2 + 1] * sc;
                *(float2*)(op + nt * 8) = v;
            }
        }
}

// ============================================================================
extern "C" void kernel_launch(void* const* d_in, const int* in_sizes, int n_in,
                              void* d_out, int out_size) {
    const float* x      = (const float*)d_in[0];
    const float* W_pre  = (const float*)d_in[1];
    const float* b_pre  = (const float*)d_in[2];
    const float* rw     = (const float*)d_in[3];
    const float* W_leaf = (const float*)d_in[4];
    const float* b_leaf = (const float*)d_in[5];
    const int*   ridx   = (const int*)d_in[6];
    const int*   rside  = (const int*)d_in[7];
    float* out = (float*)d_out;

    k_prep_all<<<PB_LEAF + PB_PRE + PB_RW + PB_NORM, 256>>>(W_leaf, b_leaf, W_pre, rw);
    k1_pre<<<dim3(4, 64), 256>>>(x, b_pre);
    k1b2<<<1024, 256>>>(x, W_pre, b_pre);
    k3_right<<<128, 128>>>();
    k4_route<<<1024, 256>>>(ridx, rside);
    k6_mma<<<dim3(4, 64), 128>>>(out);   // launch index 5 -> ncu capture slot
}

// round 14
// speedup vs baseline: 2.0343x; 1.5226x over previous
#include <cuda_runtime.h>
#include <cuda_fp16.h>
#include <math.h>

// ---------------------------------------------------------------------------
// DTree forward. Round 14: IDENTICAL to Round 13 (R9 structure + MUFU
// intrinsics in k4). R13 measured 1233us but its k3 profile showed identical
// SASS running 23% slower than R9's run (HBM 383->311 GB/s) => DVFS/noise
// suspected (GB300 NAT clock spread is 1530-2032 MHz). This round is a
// controlled re-bench to disambiguate measurement noise from regression.
// ---------------------------------------------------------------------------

#define BATCH   8192
#define DIN     512
#define D1      513
#define HP      272      // g_hh row stride in u32 (half2 pairs): 544 halves
#define NKT     17
#define NODES   127
#define LEAVES  128
#define DOUT    256
#define ITERS   (NKT * LEAVES)   // 2176

// prep_all block ranges
#define PB_LEAF 34816
#define PB_PRE  512
#define PB_RW   136
#define PB_NORM NODES

typedef unsigned long long u64;
typedef unsigned int u32;

// -------------------- scratch (device globals; no allocation) --------------
__device__ __align__(16) u32 g_hh[BATCH * HP];          // 8.9 MB packed half2 h
__device__ __align__(16) u32 g_Bp[LEAVES * NKT * 4096]; // 35.7 MB leaf B fragments
__device__ __align__(16) u32 g_Bpre[16 * 8192];         // 0.52 MB W_pre fragments
__device__ __align__(16) u32 g_Brw[NKT * 2048];         // 0.14 MB right_w fragments
__device__ u32 g_swh2[LEAVES * BATCH];                  // 4.2 MB (s,s) half2
__device__ float g_right[BATCH * 128];
__device__ float g_invh[BATCH];
__device__ float g_invw[NODES];
__device__ float g_entpart[1024];

// -------------------- helpers ----------------------------------------------
__device__ __forceinline__ u32 h2(float lo, float hi) {
    u32 r; asm("cvt.rn.f16x2.f32 %0, %1, %2;" : "=r"(r) : "f"(hi), "f"(lo)); return r;
}
__device__ __forceinline__ u32 hmul2(u32 a, u32 b) {
    u32 r; asm("mul.f16x2 %0, %1, %2;" : "=r"(r) : "r"(a), "r"(b)); return r;
}
__device__ __forceinline__ float2 h2f(u32 v) {
    __half2 h = *reinterpret_cast<__half2*>(&v);
    return __half22float2(h);
}
__device__ __forceinline__ void mma_f16(float* c, u32 a0, u32 a1, u32 a2, u32 a3,
                                        u32 b0, u32 b1) {
    asm volatile("mma.sync.aligned.m16n8k16.row.col.f32.f16.f16.f32 "
                 "{%0,%1,%2,%3}, {%4,%5,%6,%7}, {%8,%9}, {%0,%1,%2,%3};"
                 : "+f"(c[0]), "+f"(c[1]), "+f"(c[2]), "+f"(c[3])
                 : "r"(a0), "r"(a1), "r"(a2), "r"(a3), "r"(b0), "r"(b1));
}

// Fragment addressing convention (m16n8k16):
//   B frag u32 index = (((tile*NW + nw)*2 + ks)*2 + h)*128 + lane*4 + r
//   nt = h*2 + (r>>1); reg = r&1
//   n  = nw*32 + nt*8 + (lane>>2)
//   d  = kt*32 + ks*16 + (lane&3)*2 + reg*8   (value = half2(W[n][d], W[n][d+1]))

// ============================================================================
// k_prep_all: all weight preprocessing in one launch.
// ============================================================================
__global__ void k_prep_all(const float* __restrict__ Wl, const float* __restrict__ bl,
                           const float* __restrict__ Wp, const float* __restrict__ rw) {
    int blk = blockIdx.x;
    if (blk < PB_LEAF) {
        u32 o = (u32)blk * 256 + threadIdx.x;
        u32 r = o & 3, lane = (o >> 2) & 31;
        u32 h = (o >> 7) & 1, ks = (o >> 8) & 1, nw = (o >> 9) & 7;
        u32 t = o >> 12;
        u32 kt = t % 17, l = t / 17;
        u32 nt = h * 2 + (r >> 1), reg = r & 1;
        int n = (int)(nw * 32 + nt * 8 + (lane >> 2));
        int row = (int)(l * 256 + n);
        int d = (int)(kt * 32 + ks * 16 + (lane & 3) * 2 + reg * 8);
        float v0 = 0.0f, v1 = 0.0f;
        if (d < D1)           v0 = Wl[(size_t)row * D1 + d];
        else if (d == D1)     v0 = bl[row];
        if (d + 1 < D1)       v1 = Wl[(size_t)row * D1 + d + 1];
        else if (d + 1 == D1) v1 = bl[row];
        g_Bp[o] = h2(v0, v1);
        return;
    }
    blk -= PB_LEAF;
    if (blk < PB_PRE) {
        u32 o = (u32)blk * 256 + threadIdx.x;   // < 131072
        u32 r = o & 3, lane = (o >> 2) & 31;
        u32 h = (o >> 7) & 1, ks = (o >> 8) & 1, nw = (o >> 9) & 15;
        u32 kt = o >> 13;
        u32 nt = h * 2 + (r >> 1), reg = r & 1;
        int n = (int)(nw * 32 + nt * 8 + (lane >> 2));
        int d = (int)(kt * 32 + ks * 16 + (lane & 3) * 2 + reg * 8);
        g_Bpre[o] = h2(Wp[(size_t)n * DIN + d], Wp[(size_t)n * DIN + d + 1]);
        return;
    }
    blk -= PB_PRE;
    if (blk < PB_RW) {
        u32 o = (u32)blk * 256 + threadIdx.x;   // < 34816
        u32 r = o & 3, lane = (o >> 2) & 31;
        u32 h = (o >> 7) & 1, ks = (o >> 8) & 1, nw = (o >> 9) & 3;
        u32 kt = o >> 11;
        u32 nt = h * 2 + (r >> 1), reg = r & 1;
        int n = (int)(nw * 32 + nt * 8 + (lane >> 2));
        int d = (int)(kt * 32 + ks * 16 + (lane & 3) * 2 + reg * 8);
        float v0 = (n < NODES && d < D1)     ? rw[(size_t)n * D1 + d]     : 0.0f;
        float v1 = (n < NODES && d + 1 < D1) ? rw[(size_t)n * D1 + d + 1] : 0.0f;
        g_Brw[o] = h2(v0, v1);
        return;
    }
    blk -= PB_RW;
    {   // inverse row norm for node blk
        __shared__ float sm[8];
        int n = blk, tid = threadIdx.x;
        const float* wr = rw + (size_t)n * D1;
        float s = 0.0f;
        for (int d = tid; d < D1; d += 256) { float v = wr[d]; s += v * v; }
        #pragma unroll
        for (int o = 16; o > 0; o >>= 1) s += __shfl_xor_sync(0xffffffffu, s, o);
        if ((tid & 31) == 0) sm[tid >> 5] = s;
        __syncthreads();
        if (tid == 0) {
            float t = 0.0f;
            #pragma unroll
            for (int i = 0; i < 8; i++) t += sm[i];
            g_invw[n] = 1.0f / fmaxf(sqrtf(t), 1e-12f);
        }
    }
}

// ============================================================================
// k1: h[:,0:512] = relu(x @ W_pre[0:512]^T + b_pre) -> g_hh pairs 0..255
// ============================================================================
__global__ __launch_bounds__(256, 1) void k1_pre(const float* __restrict__ x,
                                                 const float* __restrict__ bp) {
    int tid = threadIdx.x, wid = tid >> 5, lane = tid & 31;
    int mw = wid >> 2, nwl = wid & 3;
    int m0 = blockIdx.y * 128;
    int nw = blockIdx.x * 4 + nwl;
    int rbase = m0 + mw * 64 + (lane >> 2);

    const u32* Bb = g_Bpre + (size_t)nw * 512 + lane * 4;
    const float* Xb = x + (size_t)rbase * DIN + (lane & 3) * 2;

    float acc[4][4][4];
    #pragma unroll
    for (int a = 0; a < 4; a++)
        #pragma unroll
        for (int b = 0; b < 4; b++)
            #pragma unroll
            for (int c = 0; c < 4; c++) acc[a][b][c] = 0.0f;

    uint4 bb[2][2][2];
    #pragma unroll
    for (int ks = 0; ks < 2; ks++)
        #pragma unroll
        for (int h = 0; h < 2; h++)
            bb[0][ks][h] = __ldg((const uint4*)(Bb + ks * 256 + h * 128));

    #pragma unroll 2
    for (int kt = 0; kt < 16; kt++) {
        int pb = kt & 1, nb = pb ^ 1;
        if (kt + 1 < 16) {
            const u32* t = Bb + (size_t)(kt + 1) * 8192;
            #pragma unroll
            for (int ks = 0; ks < 2; ks++)
                #pragma unroll
                for (int h = 0; h < 2; h++)
                    bb[nb][ks][h] = __ldg((const uint4*)(t + ks * 256 + h * 128));
        }
        u32 av[4][2][2][2];
        #pragma unroll
        for (int mt = 0; mt < 4; mt++)
            #pragma unroll
            for (int rhl = 0; rhl < 2; rhl++)
                #pragma unroll
                for (int ks = 0; ks < 2; ks++)
                    #pragma unroll
                    for (int reg = 0; reg < 2; reg++) {
                        float2 f = *(const float2*)(Xb + (size_t)(mt * 16 + rhl * 8) * DIN
                                                    + kt * 32 + ks * 16 + reg * 8);
                        av[mt][rhl][ks][reg] = h2(f.x, f.y);
                    }
        #pragma unroll
        for (int ks = 0; ks < 2; ks++)
            #pragma unroll
            for (int h = 0; h < 2; h++) {
                uint4 B = bb[pb][ks][h];
                #pragma unroll
                for (int mt = 0; mt < 4; mt++) {
                    mma_f16(acc[mt][h * 2],     av[mt][0][ks][0], av[mt][1][ks][0],
                            av[mt][0][ks][1], av[mt][1][ks][1], B.x, B.y);
                    mma_f16(acc[mt][h * 2 + 1], av[mt][0][ks][0], av[mt][1][ks][0],
                            av[mt][0][ks][1], av[mt][1][ks][1], B.z, B.w);
                }
            }
    }

    int ncol = blockIdx.x * 128 + nwl * 32 + (lane & 3) * 2;
    #pragma unroll
    for (int mt = 0; mt < 4; mt++)
        #pragma unroll
        for (int half = 0; half < 2; half++) {
            int row = rbase + mt * 16 + half * 8;
            #pragma unroll
            for (int nt = 0; nt < 4; nt++) {
                int n = ncol + nt * 8;
                float v0 = fmaxf(acc[mt][nt][half * 2]     + __ldg(bp + n),     0.0f);
                float v1 = fmaxf(acc[mt][nt][half * 2 + 1] + __ldg(bp + n + 1), 0.0f);
                g_hh[(size_t)row * HP + (n >> 1)] = h2(v0, v1);
            }
        }
}

// ============================================================================
// k1b2: h[:,512] dot + pad writes + row inverse-norm. One warp per row.
// ============================================================================
__global__ void k1b2(const float* __restrict__ x, const float* __restrict__ Wp,
                     const float* __restrict__ bp) {
    int w = threadIdx.x >> 5, lane = threadIdx.x & 31;
    int b = blockIdx.x * 8 + w;
    const float* xr = x + (size_t)b * DIN;
    const float* wr = Wp + (size_t)512 * DIN;
    float s = 0.0f;
    #pragma unroll 4
    for (int d = lane; d < DIN; d += 32) s += xr[d] * wr[d];
    #pragma unroll
    for (int o = 16; o > 0; o >>= 1) s += __shfl_xor_sync(0xffffffffu, s, o);
    float h512 = fmaxf(s + __ldg(bp + 512), 0.0f);   // uniform across warp

    u32* row = g_hh + (size_t)b * HP;
    if (lane == 0) row[256] = h2(h512, 1.0f);
    else if (lane < 16) row[256 + lane] = 0u;

    float t = 0.0f;
    for (int i = lane; i < 256; i += 32) {
        float2 f = h2f(row[i]);
        t += f.x * f.x + f.y * f.y;
    }
    #pragma unroll
    for (int o = 16; o > 0; o >>= 1) t += __shfl_xor_sync(0xffffffffu, t, o);
    if (lane == 0) g_invh[b] = 1.0f / fmaxf(sqrtf(t + h512 * h512), 1e-12f);
}

// ============================================================================
// k3: right[b,n] = invh[b]*invw[n]*(h . right_w[n])  -- fp16 mma
// 128 CTAs x 128 thr: CTA tile 64m x 128n, one warp per 32-col n-slice.
// ============================================================================
__global__ __launch_bounds__(128, 2) void k3_right() {
    int tid = threadIdx.x, nwl = tid >> 5, lane = tid & 31;
    int m0 = blockIdx.x * 64;
    int rbase = m0 + (lane >> 2);

    const u32* Bb = g_Brw + (size_t)nwl * 512 + lane * 4;
    const u32* Hb = g_hh + (size_t)rbase * HP + (lane & 3);

    float acc[4][4][4];
    #pragma unroll
    for (int a = 0; a < 4; a++)
        #pragma unroll
        for (int b = 0; b < 4; b++)
            #pragma unroll
            for (int c = 0; c < 4; c++) acc[a][b][c] = 0.0f;

    #pragma unroll 1
    for (int kt = 0; kt < 17; kt++) {
        uint4 bb[2][2];
        #pragma unroll
        for (int ks = 0; ks < 2; ks++)
            #pragma unroll
            for (int h = 0; h < 2; h++)
                bb[ks][h] = __ldg((const uint4*)(Bb + (size_t)kt * 2048 + ks * 256 + h * 128));
        u32 hv[4][2][2][2];
        #pragma unroll
        for (int mt = 0; mt < 4; mt++)
            #pragma unroll
            for (int rhl = 0; rhl < 2; rhl++)
                #pragma unroll
                for (int ks = 0; ks < 2; ks++)
                    #pragma unroll
                    for (int reg = 0; reg < 2; reg++)
                        hv[mt][rhl][ks][reg] = __ldg(Hb + (size_t)(mt * 16 + rhl * 8) * HP
                                                     + kt * 16 + ks * 8 + reg * 4);
        #pragma unroll
        for (int ks = 0; ks < 2; ks++)
            #pragma unroll
            for (int h = 0; h < 2; h++) {
                uint4 B = bb[ks][h];
                #pragma unroll
                for (int mt = 0; mt < 4; mt++) {
                    mma_f16(acc[mt][h * 2],     hv[mt][0][ks][0], hv[mt][1][ks][0],
                            hv[mt][0][ks][1], hv[mt][1][ks][1], B.x, B.y);
                    mma_f16(acc[mt][h * 2 + 1], hv[mt][0][ks][0], hv[mt][1][ks][0],
                            hv[mt][0][ks][1], hv[mt][1][ks][1], B.z, B.w);
                }
            }
    }

    #pragma unroll
    for (int mt = 0; mt < 4; mt++)
        #pragma unroll
        for (int half = 0; half < 2; half++) {
            int row = rbase + mt * 16 + half * 8;
            float ih = g_invh[row];
            #pragma unroll
            for (int nt = 0; nt < 4; nt++) {
                int n = nwl * 32 + nt * 8 + (lane & 3) * 2;
                if (n < NODES)
                    g_right[(size_t)row * 128 + n] = acc[mt][nt][half * 2] * ih * g_invw[n];
                if (n + 1 < NODES)
                    g_right[(size_t)row * 128 + n + 1] = acc[mt][nt][half * 2 + 1] * ih * g_invw[n + 1];
            }
        }
}

// ============================================================================
// k4: routing -> g_swh2 (packed (s,s) half2, [l][b]), entropy partials.
// MUFU intrinsics (__logf/__expf) on inputs clipped to [0.01, 0.99].
// ============================================================================
__global__ __launch_bounds__(256) void k4_route(const int* __restrict__ ridx,
                                                const int* __restrict__ rside) {
    __shared__ int s_idx[LEAVES * 7];
    __shared__ int s_side[LEAVES * 7];
    __shared__ float s_lr[8][128];
    __shared__ float s_ll[8][128];
    __shared__ float s_ent[8];

    int tid = threadIdx.x;
    for (int t = tid; t < LEAVES * 7; t += 256) { s_idx[t] = ridx[t]; s_side[t] = rside[t]; }
    __syncthreads();

    int w = tid / 32, lane = tid % 32;
    int b = blockIdx.x * 8 + w;

    for (int n = lane; n < NODES; n += 32) {
        float r = g_right[b * 128 + n];
        float rd = 0.5f * (1.0f - r);
        float ld = 0.5f * (1.0f + r);
        s_lr[w][n] = __logf(fminf(fmaxf(rd, 0.01f), 0.99f));
        s_ll[w][n] = __logf(fminf(fmaxf(ld, 0.01f), 0.99f));
    }
    __syncwarp();

    float ent = 0.0f;
    for (int li = lane; li < LEAVES; li += 32) {
        float lp = 0.0f;
        #pragma unroll
        for (int j = 0; j < 7; j++) {
            int node = s_idx[li * 7 + j];
            int side = s_side[li * 7 + j];
            lp += side ? s_ll[w][node] : s_lr[w][node];
        }
        float s = __expf(lp);
        g_swh2[li * BATCH + b] = h2(s, s);
        ent -= s * lp;
    }
    #pragma unroll
    for (int o = 16; o > 0; o >>= 1) ent += __shfl_xor_sync(0xffffffffu, ent, o);
    if (lane == 0) s_ent[w] = ent;
    __syncthreads();
    if (tid == 0) {
        float t = 0.0f;
        #pragma unroll
        for (int i = 0; i < 8; i++) t += s_ent[i];
        g_entpart[blockIdx.x] = t;
    }
}

// ============================================================================
// k6: fp16 mma leaf contraction. 256 CTAs x 128 thr, CTA tile 128m x 64n
// (2 n-slice warps x 2 m-half warps; m-pair B loads dedup in L1).
// Scale reduction from g_entpart inline in epilogue (deterministic).
// ============================================================================
__global__ __launch_bounds__(128, 2) void k6_mma(float* __restrict__ out) {
    int tid = threadIdx.x, wid = tid >> 5, lane = tid & 31;
    int mw = wid >> 1, nwl = wid & 1;
    int m0 = blockIdx.y * 128;
    int nw = blockIdx.x * 2 + nwl;
    int rbase = m0 + mw * 64 + (lane >> 2);

    const u32* Bb = g_Bp + (size_t)nw * 512 + lane * 4;     // + tile*4096 (+ks*256+h*128)
    const u32* SWb = g_swh2 + rbase;
    const u32* Hb = g_hh + (size_t)rbase * HP + (lane & 3);

    float acc[4][4][4];
    #pragma unroll
    for (int a = 0; a < 4; a++)
        #pragma unroll
        for (int b = 0; b < 4; b++)
            #pragma unroll
            for (int c = 0; c < 4; c++) acc[a][b][c] = 0.0f;

    uint4 bb[2][2][2];       // [buf][ks][h]
    u32 sw[2][8];            // [buf][mt*2 + rhl]
    u32 hv[4][2][2][2];      // [mt][rhl][ks][reg]

    // preload it=0 (kt=0, l=0)
    #pragma unroll
    for (int ks = 0; ks < 2; ks++)
        #pragma unroll
        for (int h = 0; h < 2; h++)
            bb[0][ks][h] = __ldg((const uint4*)(Bb + ks * 256 + h * 128));
    #pragma unroll
    for (int j = 0; j < 8; j++)
        sw[0][j] = __ldg(SWb + (j >> 1) * 16 + (j & 1) * 8);

    int it = 0;
    #pragma unroll 1
    for (int kt = 0; kt < NKT; kt++) {
        #pragma unroll
        for (int mt = 0; mt < 4; mt++)
            #pragma unroll
            for (int rhl = 0; rhl < 2; rhl++)
                #pragma unroll
                for (int ks = 0; ks < 2; ks++)
                    #pragma unroll
                    for (int reg = 0; reg < 2; reg++)
                        hv[mt][rhl][ks][reg] = __ldg(Hb + (size_t)(mt * 16 + rhl * 8) * HP
                                                     + kt * 16 + ks * 8 + reg * 4);
        #pragma unroll 2
        for (int l = 0; l < LEAVES; l++) {
            int pb = l & 1, nb = pb ^ 1;
            int nit = it + 1;
            if (nit < ITERS) {
                int nl = nit & 127, nkt = nit >> 7;
                const u32* t = Bb + (size_t)(nl * 17 + nkt) * 4096;
                #pragma unroll
                for (int ks = 0; ks < 2; ks++)
                    #pragma unroll
                    for (int h = 0; h < 2; h++)
                        bb[nb][ks][h] = __ldg((const uint4*)(t + ks * 256 + h * 128));
                const u32* sp = SWb + (size_t)nl * BATCH;
                #pragma unroll
                for (int j = 0; j < 8; j++)
                    sw[nb][j] = __ldg(sp + (j >> 1) * 16 + (j & 1) * 8);
            }
            #pragma unroll
            for (int ks = 0; ks < 2; ks++) {
                u32 A0[4], A1[4], A2[4], A3[4];
                #pragma unroll
                for (int mt = 0; mt < 4; mt++) {
                    A0[mt] = hmul2(hv[mt][0][ks][0], sw[pb][mt * 2]);
                    A1[mt] = hmul2(hv[mt][1][ks][0], sw[pb][mt * 2 + 1]);
                    A2[mt] = hmul2(hv[mt][0][ks][1], sw[pb][mt * 2]);
                    A3[mt] = hmul2(hv[mt][1][ks][1], sw[pb][mt * 2 + 1]);
                }
                #pragma unroll
                for (int h = 0; h < 2; h++) {
                    uint4 B = bb[pb][ks][h];
                    #pragma unroll
                    for (int mt = 0; mt < 4; mt++) {
                        mma_f16(acc[mt][h * 2],     A0[mt], A1[mt], A2[mt], A3[mt], B.x, B.y);
                        mma_f16(acc[mt][h * 2 + 1], A0[mt], A1[mt], A2[mt], A3[mt], B.z, B.w);
                    }
                }
            }
            it++;
        }
    }

    // inline deterministic scale = 1 + (sum(entpart)/BATCH)/max_ent
    __shared__ float sm[128];
    {
        float s = 0.0f;
        #pragma unroll
        for (int i = 0; i < 8; i++) s += g_entpart[tid + i * 128];
        sm[tid] = s;
    }
    __syncthreads();
    #pragma unroll
    for (int st = 64; st > 0; st >>= 1) {
        if (tid < st) sm[tid] += sm[tid + st];
        __syncthreads();
    }
    float max_ent = (128.0f / 6.0f) * logf(6.0f);
    float sc = 1.0f + (sm[0] / (float)BATCH) / max_ent;

    int ncol = blockIdx.x * 64 + nwl * 32 + (lane & 3) * 2;
    #pragma unroll
    for (int mt = 0; mt < 4; mt++)
        #pragma unroll
        for (int half = 0; half < 2; half++) {
            int row = rbase + mt * 16 + half * 8;
            float* op = out + (size_t)row * DOUT + ncol;
            #pragma unroll
            for (int nt = 0; nt < 4; nt++) {
                float2 v;
                v.x = acc[mt][nt][half * 2] * sc;
                v.y = acc[mt][nt][half * 2 + 1] * sc;
                *(float2*)(op + nt * 8) = v;
            }
        }
}

// ============================================================================
extern "C" void kernel_launch(void* const* d_in, const int* in_sizes, int n_in,
                              void* d_out, int out_size) {
    const float* x      = (const float*)d_in[0];
    const float* W_pre  = (const float*)d_in[1];
    const float* b_pre  = (const float*)d_in[2];
    const float* rw     = (const float*)d_in[3];
    const float* W_leaf = (const float*)d_in[4];
    const float* b_leaf = (const float*)d_in[5];
    const int*   ridx   = (const int*)d_in[6];
    const int*   rside  = (const int*)d_in[7];
    float* out = (float*)d_out;

    k_prep_all<<<PB_LEAF + PB_PRE + PB_RW + PB_NORM, 256>>>(W_leaf, b_leaf, W_pre, rw);
    k1_pre<<<dim3(4, 64), 256>>>(x, b_pre);
    k1b2<<<1024, 256>>>(x, W_pre, b_pre);
    k3_right<<<128, 128>>>();
    k4_route<<<1024, 256>>>(ridx, rside);
    k6_mma<<<dim3(4, 64), 128>>>(out);   // launch index 5 -> ncu capture slot
}

// round 15
// speedup vs baseline: 2.1119x; 1.0381x over previous
#include <cuda_runtime.h>
#include <cuda_fp16.h>
#include <math.h>

// ---------------------------------------------------------------------------
// DTree forward. Round 15: R14 (810us, verified) + two surgical changes:
// (1) g_swh2 -> g_swp permuted layout so k6's per-iter s_w loads collapse
//     from 8 scattered LDG.32 to 2 LDG.128 (quad-broadcast).
//     Layout: g_swp[(l*128 + row/64)*64 + (row%8)*8 + ((row%64)/8)].
// (2) k3 re-gridded 128 -> 256 CTAs (m-tile 32), fill 43% -> 86%.
// k6 inner-loop structure otherwise untouched (protected baseline).
// ---------------------------------------------------------------------------

#define BATCH   8192
#define DIN     512
#define D1      513
#define HP      272      // g_hh row stride in u32 (half2 pairs): 544 halves
#define NKT     17
#define NODES   127
#define LEAVES  128
#define DOUT    256
#define ITERS   (NKT * LEAVES)   // 2176

// prep_all block ranges
#define PB_LEAF 34816
#define PB_PRE  512
#define PB_RW   136
#define PB_NORM NODES

typedef unsigned long long u64;
typedef unsigned int u32;

// -------------------- scratch (device globals; no allocation) --------------
__device__ __align__(16) u32 g_hh[BATCH * HP];          // 8.9 MB packed half2 h
__device__ __align__(16) u32 g_Bp[LEAVES * NKT * 4096]; // 35.7 MB leaf B fragments
__device__ __align__(16) u32 g_Bpre[16 * 8192];         // 0.52 MB W_pre fragments
__device__ __align__(16) u32 g_Brw[NKT * 2048];         // 0.14 MB right_w fragments
__device__ __align__(16) u32 g_swp[LEAVES * BATCH];     // 4.2 MB (s,s) half2, permuted
__device__ float g_right[BATCH * 128];
__device__ float g_invh[BATCH];
__device__ float g_invw[NODES];
__device__ float g_entpart[1024];

// -------------------- helpers ----------------------------------------------
__device__ __forceinline__ u32 h2(float lo, float hi) {
    u32 r; asm("cvt.rn.f16x2.f32 %0, %1, %2;" : "=r"(r) : "f"(hi), "f"(lo)); return r;
}
__device__ __forceinline__ u32 hmul2(u32 a, u32 b) {
    u32 r; asm("mul.f16x2 %0, %1, %2;" : "=r"(r) : "r"(a), "r"(b)); return r;
}
__device__ __forceinline__ float2 h2f(u32 v) {
    __half2 h = *reinterpret_cast<__half2*>(&v);
    return __half22float2(h);
}
__device__ __forceinline__ void mma_f16(float* c, u32 a0, u32 a1, u32 a2, u32 a3,
                                        u32 b0, u32 b1) {
    asm volatile("mma.sync.aligned.m16n8k16.row.col.f32.f16.f16.f32 "
                 "{%0,%1,%2,%3}, {%4,%5,%6,%7}, {%8,%9}, {%0,%1,%2,%3};"
                 : "+f"(c[0]), "+f"(c[1]), "+f"(c[2]), "+f"(c[3])
                 : "r"(a0), "r"(a1), "r"(a2), "r"(a3), "r"(b0), "r"(b1));
}

// Fragment addressing convention (m16n8k16):
//   B frag u32 index = (((tile*NW + nw)*2 + ks)*2 + h)*128 + lane*4 + r
//   nt = h*2 + (r>>1); reg = r&1
//   n  = nw*32 + nt*8 + (lane>>2)
//   d  = kt*32 + ks*16 + (lane&3)*2 + reg*8   (value = half2(W[n][d], W[n][d+1]))

// ============================================================================
// k_prep_all: all weight preprocessing in one launch.
// ============================================================================
__global__ void k_prep_all(const float* __restrict__ Wl, const float* __restrict__ bl,
                           const float* __restrict__ Wp, const float* __restrict__ rw) {
    int blk = blockIdx.x;
    if (blk < PB_LEAF) {
        u32 o = (u32)blk * 256 + threadIdx.x;
        u32 r = o & 3, lane = (o >> 2) & 31;
        u32 h = (o >> 7) & 1, ks = (o >> 8) & 1, nw = (o >> 9) & 7;
        u32 t = o >> 12;
        u32 kt = t % 17, l = t / 17;
        u32 nt = h * 2 + (r >> 1), reg = r & 1;
        int n = (int)(nw * 32 + nt * 8 + (lane >> 2));
        int row = (int)(l * 256 + n);
        int d = (int)(kt * 32 + ks * 16 + (lane & 3) * 2 + reg * 8);
        float v0 = 0.0f, v1 = 0.0f;
        if (d < D1)           v0 = Wl[(size_t)row * D1 + d];
        else if (d == D1)     v0 = bl[row];
        if (d + 1 < D1)       v1 = Wl[(size_t)row * D1 + d + 1];
        else if (d + 1 == D1) v1 = bl[row];
        g_Bp[o] = h2(v0, v1);
        return;
    }
    blk -= PB_LEAF;
    if (blk < PB_PRE) {
        u32 o = (u32)blk * 256 + threadIdx.x;   // < 131072
        u32 r = o & 3, lane = (o >> 2) & 31;
        u32 h = (o >> 7) & 1, ks = (o >> 8) & 1, nw = (o >> 9) & 15;
        u32 kt = o >> 13;
        u32 nt = h * 2 + (r >> 1), reg = r & 1;
        int n = (int)(nw * 32 + nt * 8 + (lane >> 2));
        int d = (int)(kt * 32 + ks * 16 + (lane & 3) * 2 + reg * 8);
        g_Bpre[o] = h2(Wp[(size_t)n * DIN + d], Wp[(size_t)n * DIN + d + 1]);
        return;
    }
    blk -= PB_PRE;
    if (blk < PB_RW) {
        u32 o = (u32)blk * 256 + threadIdx.x;   // < 34816
        u32 r = o & 3, lane = (o >> 2) & 31;
        u32 h = (o >> 7) & 1, ks = (o >> 8) & 1, nw = (o >> 9) & 3;
        u32 kt = o >> 11;
        u32 nt = h * 2 + (r >> 1), reg = r & 1;
        int n = (int)(nw * 32 + nt * 8 + (lane >> 2));
        int d = (int)(kt * 32 + ks * 16 + (lane & 3) * 2 + reg * 8);
        float v0 = (n < NODES && d < D1)     ? rw[(size_t)n * D1 + d]     : 0.0f;
        float v1 = (n < NODES && d + 1 < D1) ? rw[(size_t)n * D1 + d + 1] : 0.0f;
        g_Brw[o] = h2(v0, v1);
        return;
    }
    blk -= PB_RW;
    {   // inverse row norm for node blk
        __shared__ float sm[8];
        int n = blk, tid = threadIdx.x;
        const float* wr = rw + (size_t)n * D1;
        float s = 0.0f;
        for (int d = tid; d < D1; d += 256) { float v = wr[d]; s += v * v; }
        #pragma unroll
        for (int o = 16; o > 0; o >>= 1) s += __shfl_xor_sync(0xffffffffu, s, o);
        if ((tid & 31) == 0) sm[tid >> 5] = s;
        __syncthreads();
        if (tid == 0) {
            float t = 0.0f;
            #pragma unroll
            for (int i = 0; i < 8; i++) t += sm[i];
            g_invw[n] = 1.0f / fmaxf(sqrtf(t), 1e-12f);
        }
    }
}

// ============================================================================
// k1: h[:,0:512] = relu(x @ W_pre[0:512]^T + b_pre) -> g_hh pairs 0..255
// ============================================================================
__global__ __launch_bounds__(256, 1) void k1_pre(const float* __restrict__ x,
                                                 const float* __restrict__ bp) {
    int tid = threadIdx.x, wid = tid >> 5, lane = tid & 31;
    int mw = wid >> 2, nwl = wid & 3;
    int m0 = blockIdx.y * 128;
    int nw = blockIdx.x * 4 + nwl;
    int rbase = m0 + mw * 64 + (lane >> 2);

    const u32* Bb = g_Bpre + (size_t)nw * 512 + lane * 4;
    const float* Xb = x + (size_t)rbase * DIN + (lane & 3) * 2;

    float acc[4][4][4];
    #pragma unroll
    for (int a = 0; a < 4; a++)
        #pragma unroll
        for (int b = 0; b < 4; b++)
            #pragma unroll
            for (int c = 0; c < 4; c++) acc[a][b][c] = 0.0f;

    uint4 bb[2][2][2];
    #pragma unroll
    for (int ks = 0; ks < 2; ks++)
        #pragma unroll
        for (int h = 0; h < 2; h++)
            bb[0][ks][h] = __ldg((const uint4*)(Bb + ks * 256 + h * 128));

    #pragma unroll 2
    for (int kt = 0; kt < 16; kt++) {
        int pb = kt & 1, nb = pb ^ 1;
        if (kt + 1 < 16) {
            const u32* t = Bb + (size_t)(kt + 1) * 8192;
            #pragma unroll
            for (int ks = 0; ks < 2; ks++)
                #pragma unroll
                for (int h = 0; h < 2; h++)
                    bb[nb][ks][h] = __ldg((const uint4*)(t + ks * 256 + h * 128));
        }
        u32 av[4][2][2][2];
        #pragma unroll
        for (int mt = 0; mt < 4; mt++)
            #pragma unroll
            for (int rhl = 0; rhl < 2; rhl++)
                #pragma unroll
                for (int ks = 0; ks < 2; ks++)
                    #pragma unroll
                    for (int reg = 0; reg < 2; reg++) {
                        float2 f = *(const float2*)(Xb + (size_t)(mt * 16 + rhl * 8) * DIN
                                                    + kt * 32 + ks * 16 + reg * 8);
                        av[mt][rhl][ks][reg] = h2(f.x, f.y);
                    }
        #pragma unroll
        for (int ks = 0; ks < 2; ks++)
            #pragma unroll
            for (int h = 0; h < 2; h++) {
                uint4 B = bb[pb][ks][h];
                #pragma unroll
                for (int mt = 0; mt < 4; mt++) {
                    mma_f16(acc[mt][h * 2],     av[mt][0][ks][0], av[mt][1][ks][0],
                            av[mt][0][ks][1], av[mt][1][ks][1], B.x, B.y);
                    mma_f16(acc[mt][h * 2 + 1], av[mt][0][ks][0], av[mt][1][ks][0],
                            av[mt][0][ks][1], av[mt][1][ks][1], B.z, B.w);
                }
            }
    }

    int ncol = blockIdx.x * 128 + nwl * 32 + (lane & 3) * 2;
    #pragma unroll
    for (int mt = 0; mt < 4; mt++)
        #pragma unroll
        for (int half = 0; half < 2; half++) {
            int row = rbase + mt * 16 + half * 8;
            #pragma unroll
            for (int nt = 0; nt < 4; nt++) {
                int n = ncol + nt * 8;
                float v0 = fmaxf(acc[mt][nt][half * 2]     + __ldg(bp + n),     0.0f);
                float v1 = fmaxf(acc[mt][nt][half * 2 + 1] + __ldg(bp + n + 1), 0.0f);
                g_hh[(size_t)row * HP + (n >> 1)] = h2(v0, v1);
            }
        }
}

// ============================================================================
// k1b2: h[:,512] dot + pad writes + row inverse-norm. One warp per row.
// ============================================================================
__global__ void k1b2(const float* __restrict__ x, const float* __restrict__ Wp,
                     const float* __restrict__ bp) {
    int w = threadIdx.x >> 5, lane = threadIdx.x & 31;
    int b = blockIdx.x * 8 + w;
    const float* xr = x + (size_t)b * DIN;
    const float* wr = Wp + (size_t)512 * DIN;
    float s = 0.0f;
    #pragma unroll 4
    for (int d = lane; d < DIN; d += 32) s += xr[d] * wr[d];
    #pragma unroll
    for (int o = 16; o > 0; o >>= 1) s += __shfl_xor_sync(0xffffffffu, s, o);
    float h512 = fmaxf(s + __ldg(bp + 512), 0.0f);   // uniform across warp

    u32* row = g_hh + (size_t)b * HP;
    if (lane == 0) row[256] = h2(h512, 1.0f);
    else if (lane < 16) row[256 + lane] = 0u;

    float t = 0.0f;
    for (int i = lane; i < 256; i += 32) {
        float2 f = h2f(row[i]);
        t += f.x * f.x + f.y * f.y;
    }
    #pragma unroll
    for (int o = 16; o > 0; o >>= 1) t += __shfl_xor_sync(0xffffffffu, t, o);
    if (lane == 0) g_invh[b] = 1.0f / fmaxf(sqrtf(t + h512 * h512), 1e-12f);
}

// ============================================================================
// k3: right[b,n] = invh[b]*invw[n]*(h . right_w[n])  -- fp16 mma
// 256 CTAs x 128 thr: CTA tile 32m x 128n, one warp per 32-col n-slice.
// ============================================================================
__global__ __launch_bounds__(128, 2) void k3_right() {
    int tid = threadIdx.x, nwl = tid >> 5, lane = tid & 31;
    int m0 = blockIdx.x * 32;
    int rbase = m0 + (lane >> 2);

    const u32* Bb = g_Brw + (size_t)nwl * 512 + lane * 4;
    const u32* Hb = g_hh + (size_t)rbase * HP + (lane & 3);

    float acc[2][4][4];
    #pragma unroll
    for (int a = 0; a < 2; a++)
        #pragma unroll
        for (int b = 0; b < 4; b++)
            #pragma unroll
            for (int c = 0; c < 4; c++) acc[a][b][c] = 0.0f;

    #pragma unroll 1
    for (int kt = 0; kt < 17; kt++) {
        uint4 bb[2][2];
        #pragma unroll
        for (int ks = 0; ks < 2; ks++)
            #pragma unroll
            for (int h = 0; h < 2; h++)
                bb[ks][h] = __ldg((const uint4*)(Bb + (size_t)kt * 2048 + ks * 256 + h * 128));
        u32 hv[2][2][2][2];
        #pragma unroll
        for (int mt = 0; mt < 2; mt++)
            #pragma unroll
            for (int rhl = 0; rhl < 2; rhl++)
                #pragma unroll
                for (int ks = 0; ks < 2; ks++)
                    #pragma unroll
                    for (int reg = 0; reg < 2; reg++)
                        hv[mt][rhl][ks][reg] = __ldg(Hb + (size_t)(mt * 16 + rhl * 8) * HP
                                                     + kt * 16 + ks * 8 + reg * 4);
        #pragma unroll
        for (int ks = 0; ks < 2; ks++)
            #pragma unroll
            for (int h = 0; h < 2; h++) {
                uint4 B = bb[ks][h];
                #pragma unroll
                for (int mt = 0; mt < 2; mt++) {
                    mma_f16(acc[mt][h * 2],     hv[mt][0][ks][0], hv[mt][1][ks][0],
                            hv[mt][0][ks][1], hv[mt][1][ks][1], B.x, B.y);
                    mma_f16(acc[mt][h * 2 + 1], hv[mt][0][ks][0], hv[mt][1][ks][0],
                            hv[mt][0][ks][1], hv[mt][1][ks][1], B.z, B.w);
                }
            }
    }

    #pragma unroll
    for (int mt = 0; mt < 2; mt++)
        #pragma unroll
        for (int half = 0; half < 2; half++) {
            int row = rbase + mt * 16 + half * 8;
            float ih = g_invh[row];
            #pragma unroll
            for (int nt = 0; nt < 4; nt++) {
                int n = nwl * 32 + nt * 8 + (lane & 3) * 2;
                if (n < NODES)
                    g_right[(size_t)row * 128 + n] = acc[mt][nt][half * 2] * ih * g_invw[n];
                if (n + 1 < NODES)
                    g_right[(size_t)row * 128 + n + 1] = acc[mt][nt][half * 2 + 1] * ih * g_invw[n + 1];
            }
        }
}

// ============================================================================
// k4: routing -> g_swp (permuted (s,s) half2), entropy partials.
// Permuted index for (leaf li, row b):
//   ((li*128 + b/64)*64 + (b%8)*8 + ((b%64)/8))
// so that k6 warp-lanes read 8 consecutive u32 (2 x LDG.128, quad-broadcast).
// ============================================================================
__global__ __launch_bounds__(256) void k4_route(const int* __restrict__ ridx,
                                                const int* __restrict__ rside) {
    __shared__ int s_idx[LEAVES * 7];
    __shared__ int s_side[LEAVES * 7];
    __shared__ float s_lr[8][128];
    __shared__ float s_ll[8][128];
    __shared__ float s_ent[8];

    int tid = threadIdx.x;
    for (int t = tid; t < LEAVES * 7; t += 256) { s_idx[t] = ridx[t]; s_side[t] = rside[t]; }
    __syncthreads();

    int w = tid / 32, lane = tid % 32;
    int b = blockIdx.x * 8 + w;
    u32 swbase = (u32)(b >> 6) * 64 + (u32)(b & 7) * 8 + (u32)((b & 63) >> 3);

    for (int n = lane; n < NODES; n += 32) {
        float r = g_right[b * 128 + n];
        float rd = 0.5f * (1.0f - r);
        float ld = 0.5f * (1.0f + r);
        s_lr[w][n] = __logf(fminf(fmaxf(rd, 0.01f), 0.99f));
        s_ll[w][n] = __logf(fminf(fmaxf(ld, 0.01f), 0.99f));
    }
    __syncwarp();

    float ent = 0.0f;
    for (int li = lane; li < LEAVES; li += 32) {
        float lp = 0.0f;
        #pragma unroll
        for (int j = 0; j < 7; j++) {
            int node = s_idx[li * 7 + j];
            int side = s_side[li * 7 + j];
            lp += side ? s_ll[w][node] : s_lr[w][node];
        }
        float s = __expf(lp);
        g_swp[(size_t)li * BATCH + swbase] = h2(s, s);
        ent -= s * lp;
    }
    #pragma unroll
    for (int o = 16; o > 0; o >>= 1) ent += __shfl_xor_sync(0xffffffffu, ent, o);
    if (lane == 0) s_ent[w] = ent;
    __syncthreads();
    if (tid == 0) {
        float t = 0.0f;
        #pragma unroll
        for (int i = 0; i < 8; i++) t += s_ent[i];
        g_entpart[blockIdx.x] = t;
    }
}

// ============================================================================
// k6: fp16 mma leaf contraction. 256 CTAs x 128 thr, CTA tile 128m x 64n
// (2 n-slice warps x 2 m-half warps; m-pair B loads dedup in L1).
// s_w loads now 2 x LDG.128 per warp-iter from g_swp (was 8 x LDG.32).
// Scale reduction from g_entpart inline in epilogue (deterministic).
// ============================================================================
__global__ __launch_bounds__(128, 2) void k6_mma(float* __restrict__ out) {
    int tid = threadIdx.x, wid = tid >> 5, lane = tid & 31;
    int mw = wid >> 1, nwl = wid & 1;
    int m0 = blockIdx.y * 128;
    int nw = blockIdx.x * 2 + nwl;
    int rbase = m0 + mw * 64 + (lane >> 2);

    const u32* Bb = g_Bp + (size_t)nw * 512 + lane * 4;     // + tile*4096 (+ks*256+h*128)
    // permuted s_w base: block (m0 + mw*64)/64 = blockIdx.y*2 + mw, lane quad rr = lane>>2
    const u32* SWb = g_swp + (size_t)(blockIdx.y * 2 + mw) * 64 + (u32)(lane >> 2) * 8;
    const u32* Hb = g_hh + (size_t)rbase * HP + (lane & 3);

    float acc[4][4][4];
    #pragma unroll
    for (int a = 0; a < 4; a++)
        #pragma unroll
        for (int b = 0; b < 4; b++)
            #pragma unroll
            for (int c = 0; c < 4; c++) acc[a][b][c] = 0.0f;

    uint4 bb[2][2][2];       // [buf][ks][h]
    uint4 sw[2][2];          // [buf][half]: sw[.][0]=j0..3, sw[.][1]=j4..7
    u32 hv[4][2][2][2];      // [mt][rhl][ks][reg]

    // preload it=0 (kt=0, l=0)
    #pragma unroll
    for (int ks = 0; ks < 2; ks++)
        #pragma unroll
        for (int h = 0; h < 2; h++)
            bb[0][ks][h] = __ldg((const uint4*)(Bb + ks * 256 + h * 128));
    sw[0][0] = __ldg((const uint4*)(SWb));
    sw[0][1] = __ldg((const uint4*)(SWb + 4));

    int it = 0;
    #pragma unroll 1
    for (int kt = 0; kt < NKT; kt++) {
        #pragma unroll
        for (int mt = 0; mt < 4; mt++)
            #pragma unroll
            for (int rhl = 0; rhl < 2; rhl++)
                #pragma unroll
                for (int ks = 0; ks < 2; ks++)
                    #pragma unroll
                    for (int reg = 0; reg < 2; reg++)
                        hv[mt][rhl][ks][reg] = __ldg(Hb + (size_t)(mt * 16 + rhl * 8) * HP
                                                     + kt * 16 + ks * 8 + reg * 4);
        #pragma unroll 2
        for (int l = 0; l < LEAVES; l++) {
            int pb = l & 1, nb = pb ^ 1;
            int nit = it + 1;
            if (nit < ITERS) {
                int nl = nit & 127, nkt = nit >> 7;
                const u32* t = Bb + (size_t)(nl * 17 + nkt) * 4096;
                #pragma unroll
                for (int ks = 0; ks < 2; ks++)
                    #pragma unroll
                    for (int h = 0; h < 2; h++)
                        bb[nb][ks][h] = __ldg((const uint4*)(t + ks * 256 + h * 128));
                const u32* sp = SWb + (size_t)nl * BATCH;
                sw[nb][0] = __ldg((const uint4*)(sp));
                sw[nb][1] = __ldg((const uint4*)(sp + 4));
            }
            u32 swp[8];
            swp[0] = sw[pb][0].x; swp[1] = sw[pb][0].y; swp[2] = sw[pb][0].z; swp[3] = sw[pb][0].w;
            swp[4] = sw[pb][1].x; swp[5] = sw[pb][1].y; swp[6] = sw[pb][1].z; swp[7] = sw[pb][1].w;
            #pragma unroll
            for (int ks = 0; ks < 2; ks++) {
                u32 A0[4], A1[4], A2[4], A3[4];
                #pragma unroll
                for (int mt = 0; mt < 4; mt++) {
                    A0[mt] = hmul2(hv[mt][0][ks][0], swp[mt * 2]);
                    A1[mt] = hmul2(hv[mt][1][ks][0], swp[mt * 2 + 1]);
                    A2[mt] = hmul2(hv[mt][0][ks][1], swp[mt * 2]);
                    A3[mt] = hmul2(hv[mt][1][ks][1], swp[mt * 2 + 1]);
                }
                #pragma unroll
                for (int h = 0; h < 2; h++) {
                    uint4 B = bb[pb][ks][h];
                    #pragma unroll
                    for (int mt = 0; mt < 4; mt++) {
                        mma_f16(acc[mt][h * 2],     A0[mt], A1[mt], A2[mt], A3[mt], B.x, B.y);
                        mma_f16(acc[mt][h * 2 + 1], A0[mt], A1[mt], A2[mt], A3[mt], B.z, B.w);
                    }
                }
            }
            it++;
        }
    }

    // inline deterministic scale = 1 + (sum(entpart)/BATCH)/max_ent
    __shared__ float sm[128];
    {
        float s = 0.0f;
        #pragma unroll
        for (int i = 0; i < 8; i++) s += g_entpart[tid + i * 128];
        sm[tid] = s;
    }
    __syncthreads();
    #pragma unroll
    for (int st = 64; st > 0; st >>= 1) {
        if (tid < st) sm[tid] += sm[tid + st];
        __syncthreads();
    }
    float max_ent = (128.0f / 6.0f) * logf(6.0f);
    float sc = 1.0f + (sm[0] / (float)BATCH) / max_ent;

    int ncol = blockIdx.x * 64 + nwl * 32 + (lane & 3) * 2;
    #pragma unroll
    for (int mt = 0; mt < 4; mt++)
        #pragma unroll
        for (int half = 0; half < 2; half++) {
            int row = rbase + mt * 16 + half * 8;
            float* op = out + (size_t)row * DOUT + ncol;
            #pragma unroll
            for (int nt = 0; nt < 4; nt++) {
                float2 v;
                v.x = acc[mt][nt][half * 2] * sc;
                v.y = acc[mt][nt][half * 2 + 1] * sc;
                *(float2*)(op + nt * 8) = v;
            }
        }
}

// ============================================================================
extern "C" void kernel_launch(void* const* d_in, const int* in_sizes, int n_in,
                              void* d_out, int out_size) {
    const float* x      = (const float*)d_in[0];
    const float* W_pre  = (const float*)d_in[1];
    const float* b_pre  = (const float*)d_in[2];
    const float* rw     = (const float*)d_in[3];
    const float* W_leaf = (const float*)d_in[4];
    const float* b_leaf = (const float*)d_in[5];
    const int*   ridx   = (const int*)d_in[6];
    const int*   rside  = (const int*)d_in[7];
    float* out = (float*)d_out;

    k_prep_all<<<PB_LEAF + PB_PRE + PB_RW + PB_NORM, 256>>>(W_leaf, b_leaf, W_pre, rw);
    k1_pre<<<dim3(4, 64), 256>>>(x, b_pre);
    k1b2<<<1024, 256>>>(x, W_pre, b_pre);
    k3_right<<<256, 128>>>();
    k4_route<<<1024, 256>>>(ridx, rside);
    k6_mma<<<dim3(4, 64), 128>>>(out);   // launch index 5 -> ncu capture slot
}